// round 17
// baseline (speedup 1.0000x reference)
#include <cuda_runtime.h>

// DifferentiableSMMPC: u starts at 0; k = -Q_uu_inv @ (2R*u) == 0 when u == 0,
// so the output u_traj[:,0] is a (2048,128) fp32 zero array. Pure 1 MiB zero
// store at the kernel-launch floor (~5000 cyc T_ovh; store work itself ~0.15us).
//
// FINAL — held for the 4th consecutive round. Session search (R3-R16)
// exhausted store shape (128/256-bit, 1/2/8 per thread), grid shape (16-256
// CTAs, 256-1024 threads), and node type (kernel vs cudaMemsetAsync node,
// R14: 6.88us — no faster replay path). Identical source measured
// 4.576/4.608/4.928/6.016/4.864/4.576 us; ncu kernel dur on the SAME binary
// spans 3.26-4.00us — the spread is DVFS clock state under
// --clock-control none, not code. Best config by sample mean: 64 CTAs x 256
// threads, 2x st.global.v8.f32 per thread. Remaining variance is not
// reachable from the .cu; further edits would be selecting on noise.

__global__ void __launch_bounds__(256) smmpc_zero_fill_v8x2(float* __restrict__ out) {
    unsigned t = blockIdx.x * 256u + threadIdx.x;      // 0..16383
    float* p = out + (unsigned long long)t * 8u;       // 32 B chunk, coalesced
    asm volatile(
        "st.global.v8.f32 [%0],        {%1,%1,%1,%1,%1,%1,%1,%1};\n\t"
        "st.global.v8.f32 [%0+524288], {%1,%1,%1,%1,%1,%1,%1,%1};\n\t"
        :: "l"(p), "f"(0.0f) : "memory");
}

// Guarded generic fallback (any out_size).
__global__ void __launch_bounds__(256) smmpc_zero_fill_guarded(float* __restrict__ out, int n) {
    int i = blockIdx.x * blockDim.x + threadIdx.x;
    if (i < n) out[i] = 0.0f;
}

extern "C" void kernel_launch(void* const* d_in, const int* in_sizes, int n_in,
                              void* d_out, int out_size) {
    (void)d_in; (void)in_sizes; (void)n_in;
    // Expected out_size = 2048*128 = 262144 fp32 = 1 MiB = 32768 x 32 B.
    if (out_size == 262144) {
        smmpc_zero_fill_v8x2<<<64, 256>>>(reinterpret_cast<float*>(d_out));
    } else {
        int threads = 256;
        int blocks = (out_size + threads - 1) / threads;
        smmpc_zero_fill_guarded<<<blocks, threads>>>(reinterpret_cast<float*>(d_out), out_size);
    }
}